// round 4
// baseline (speedup 1.0000x reference)
#include <cuda_runtime.h>
#include <cuda_bf16.h>
#include <math.h>
#include <stdint.h>

#define D_MODEL 1024
#define SEQ     2048
#define BATCH   2
#define NHEAD   16
#define DH      64
#define D3      (3 * D_MODEL)
#define MTOT    (BATCH * SEQ)   // 4096

// ---------------- scratch ----------------
__device__ float g_qkv[BATCH * SEQ * D3];
__device__ float g_attn[BATCH * SEQ * D_MODEL];
__device__ __nv_bfloat16 g_ah[MTOT * D_MODEL];
__device__ __nv_bfloat16 g_al[MTOT * D_MODEL];
__device__ __nv_bfloat16 g_bh[D3 * D_MODEL];
__device__ __nv_bfloat16 g_bl[D3 * D_MODEL];

#define NEG_INF __int_as_float(0xff800000)

// ---------------- helpers ----------------
__device__ __forceinline__ uint32_t smem_u32(const void* p) {
    uint32_t a;
    asm("{ .reg .u64 t; cvta.to.shared.u64 t, %1; cvt.u32.u64 %0, t; }" : "=r"(a) : "l"(p));
    return a;
}
__device__ __forceinline__ void cp_async16(uint32_t dst, const void* src) {
    asm volatile("cp.async.cg.shared.global [%0], [%1], 16;" :: "r"(dst), "l"(src));
}
#define CP_COMMIT() asm volatile("cp.async.commit_group;" ::: "memory")
#define CP_WAIT1()  asm volatile("cp.async.wait_group 1;" ::: "memory")

__device__ __forceinline__ void ldsm_x4(uint32_t* r, uint32_t addr) {
    asm volatile("ldmatrix.sync.aligned.m8n8.x4.shared.b16 {%0,%1,%2,%3}, [%4];"
                 : "=r"(r[0]), "=r"(r[1]), "=r"(r[2]), "=r"(r[3]) : "r"(addr));
}
__device__ __forceinline__ void mma_bf16(float* d, const uint32_t* a, const uint32_t* b) {
    asm volatile("mma.sync.aligned.m16n8k16.row.col.f32.bf16.bf16.f32 "
                 "{%0,%1,%2,%3}, {%4,%5,%6,%7}, {%8,%9}, {%0,%1,%2,%3};"
                 : "+f"(d[0]), "+f"(d[1]), "+f"(d[2]), "+f"(d[3])
                 : "r"(a[0]), "r"(a[1]), "r"(a[2]), "r"(a[3]), "r"(b[0]), "r"(b[1]));
}

// ---------------- conversion kernels ----------------
__global__ void split_kernel(const float* __restrict__ in,
                             __nv_bfloat16* __restrict__ hi,
                             __nv_bfloat16* __restrict__ lo, int n4)
{
    int i = blockIdx.x * blockDim.x + threadIdx.x;
    if (i >= n4) return;
    float4 v = reinterpret_cast<const float4*>(in)[i];
    float f[4] = {v.x, v.y, v.z, v.w};
    __nv_bfloat16 h[4], l[4];
#pragma unroll
    for (int j = 0; j < 4; j++) {
        h[j] = __float2bfloat16_rn(f[j]);
        l[j] = __float2bfloat16_rn(f[j] - __bfloat162float(h[j]));
    }
    reinterpret_cast<__nv_bfloat162*>(hi)[2*i]   = __nv_bfloat162(h[0], h[1]);
    reinterpret_cast<__nv_bfloat162*>(hi)[2*i+1] = __nv_bfloat162(h[2], h[3]);
    reinterpret_cast<__nv_bfloat162*>(lo)[2*i]   = __nv_bfloat162(l[0], l[1]);
    reinterpret_cast<__nv_bfloat162*>(lo)[2*i+1] = __nv_bfloat162(l[2], l[3]);
}

__global__ void transpose_split_kernel(const float* __restrict__ W,
                                       __nv_bfloat16* __restrict__ th,
                                       __nv_bfloat16* __restrict__ tl,
                                       int K, int N)
{
    __shared__ float t[32][33];
    int k0 = blockIdx.y * 32, n0 = blockIdx.x * 32;
    int tx = threadIdx.x, ty = threadIdx.y;
#pragma unroll
    for (int r = 0; r < 4; r++) {
        int row = ty + r * 8;
        t[row][tx] = W[(size_t)(k0 + row) * N + n0 + tx];
    }
    __syncthreads();
#pragma unroll
    for (int r = 0; r < 4; r++) {
        int nn = ty + r * 8;
        float v = t[tx][nn];
        __nv_bfloat16 h = __float2bfloat16_rn(v);
        __nv_bfloat16 l = __float2bfloat16_rn(v - __bfloat162float(h));
        size_t o = (size_t)(n0 + nn) * K + k0 + tx;
        th[o] = h;
        tl[o] = l;
    }
}

// ---------------- mma.sync bf16x3 GEMM ----------------
// C[M,N] fp32 = (Ah+Al)[M,K] * (Bh+Bl)[N,K]^T, dropping Al*Bl.
// 256 threads, 128x128 tile, BK=32, double-buffered cp.async.
// smem rows padded to 40 bf16 (80B stride, conflict-free ldmatrix).
#define ROWP 40
#define TILE_ELEMS (128 * ROWP)             // 5120 bf16
#define TILE_BYTES (TILE_ELEMS * 2)         // 10240 B
#define STAGE_ELEMS (4 * TILE_ELEMS)
#define GEMM_SMEM (2 * 4 * TILE_BYTES)      // 81920 B

__global__ __launch_bounds__(256) void gemm_mma(
    const __nv_bfloat16* __restrict__ Ah, const __nv_bfloat16* __restrict__ Al,
    const __nv_bfloat16* __restrict__ Bh, const __nv_bfloat16* __restrict__ Bl,
    float* __restrict__ C, int M, int N, int K)
{
    extern __shared__ __nv_bfloat16 sm[];
    const uint32_t sb = smem_u32(sm);
    const int tid = threadIdx.x;
    const int lane = tid & 31, warp = tid >> 5;
    const int wm = warp & 1, wn = warp >> 1;       // 2x4 warp grid
    const int cRow = blockIdx.y * 128, cCol = blockIdx.x * 128;
    const int KSTEPS = K / 32;

    // per-thread ldmatrix address offsets (within a tile)
    const int tg = lane >> 3, tr = lane & 7;
    const int a_row = ((tg & 1) << 3) + tr, a_col = (tg >> 1) << 3;  // A frag
    const int b_row = ((tg >> 1) << 3) + tr, b_col = (tg & 1) << 3;  // B frag pair

    float acc[4][4][4];
#pragma unroll
    for (int i = 0; i < 4; i++)
#pragma unroll
        for (int j = 0; j < 4; j++)
#pragma unroll
            for (int c = 0; c < 4; c++) acc[i][j][c] = 0.f;

    auto load_stage = [&](int stage, int k0) {
        const __nv_bfloat16* src[4] = {Ah, Al, Bh, Bl};
        const int r0[4] = {cRow, cRow, cCol, cCol};
#pragma unroll
        for (int t = 0; t < 4; t++) {
            uint32_t base = sb + (stage * 4 + t) * TILE_BYTES;
#pragma unroll
            for (int i = 0; i < 2; i++) {
                int g = i * 256 + tid;
                int row = g >> 2, c4 = g & 3;
                cp_async16(base + (row * ROWP + c4 * 8) * 2,
                           src[t] + (size_t)(r0[t] + row) * K + k0 + c4 * 8);
            }
        }
        CP_COMMIT();
    };

    load_stage(0, 0);
    load_stage(1, 32);

    for (int ks = 0; ks < KSTEPS; ks++) {
        CP_WAIT1();
        __syncthreads();
        const int stage = ks & 1;
        const uint32_t stb = sb + stage * 4 * TILE_BYTES;

#pragma unroll
        for (int k16 = 0; k16 < 2; k16++) {
            const int kc = k16 * 16;
            uint32_t ah[4][4], al[4][4], bh[4][2], bl[4][2];
#pragma unroll
            for (int mi = 0; mi < 4; mi++) {
                int row = wm * 64 + mi * 16 + a_row;
                uint32_t off = (uint32_t)(row * ROWP + kc + a_col) * 2;
                ldsm_x4(ah[mi], stb + off);                     // Ah tile 0
                ldsm_x4(al[mi], stb + TILE_BYTES + off);        // Al tile 1
            }
#pragma unroll
            for (int p = 0; p < 2; p++) {
                int row = wn * 32 + p * 16 + b_row;
                uint32_t off = (uint32_t)(row * ROWP + kc + b_col) * 2;
                uint32_t rh[4], rl[4];
                ldsm_x4(rh, stb + 2 * TILE_BYTES + off);        // Bh tile 2
                ldsm_x4(rl, stb + 3 * TILE_BYTES + off);        // Bl tile 3
                bh[2*p][0] = rh[0]; bh[2*p][1] = rh[1];
                bh[2*p+1][0] = rh[2]; bh[2*p+1][1] = rh[3];
                bl[2*p][0] = rl[0]; bl[2*p][1] = rl[1];
                bl[2*p+1][0] = rl[2]; bl[2*p+1][1] = rl[3];
            }
#pragma unroll
            for (int mi = 0; mi < 4; mi++)
#pragma unroll
                for (int ni = 0; ni < 4; ni++) {
                    mma_bf16(acc[mi][ni], ah[mi], bh[ni]);
                    mma_bf16(acc[mi][ni], ah[mi], bl[ni]);
                    mma_bf16(acc[mi][ni], al[mi], bh[ni]);
                }
        }
        __syncthreads();
        if (ks + 2 < KSTEPS) load_stage(stage, (ks + 2) * 32);
        else CP_COMMIT();   // keep group count consistent
    }

    // epilogue: direct stores (thread t of frag: rows t/4, t/4+8; cols 2*(t%4))
    const int er = lane >> 2, ec = (lane & 3) * 2;
#pragma unroll
    for (int mi = 0; mi < 4; mi++) {
#pragma unroll
        for (int ni = 0; ni < 4; ni++) {
            int row = cRow + wm * 64 + mi * 16 + er;
            int col = cCol + wn * 32 + ni * 8 + ec;
            *reinterpret_cast<float2*>(C + (size_t)row * N + col) =
                make_float2(acc[mi][ni][0], acc[mi][ni][1]);
            *reinterpret_cast<float2*>(C + (size_t)(row + 8) * N + col) =
                make_float2(acc[mi][ni][2], acc[mi][ni][3]);
        }
    }
}

// ---------------- flash attention (unchanged R2) ----------------
__global__ __launch_bounds__(256) void attn_kernel(
    const float* __restrict__ qkv, float* __restrict__ attn_out)
{
    __shared__ float Qt[64 * 64];
    __shared__ float KPt[64 * 64];
    __shared__ float Vs[64 * 64];

    const int qb = blockIdx.x;
    const int h  = blockIdx.y;
    const int b  = blockIdx.z;
    const int tid = threadIdx.x;

    const int ty = (tid >> 4) * 4;
    const int tx = (tid & 15) * 4;
    const int li = tid & 63;
    const int q4 = tid >> 6;

    const size_t base = (size_t)(b * SEQ) * D3 + h * DH;

    {
        const float* qr = qkv + base + (size_t)(qb * 64 + li) * D3 + q4 * 16;
#pragma unroll
        for (int c = 0; c < 4; c++) {
            float4 v = *reinterpret_cast<const float4*>(qr + c * 4);
            int d = q4 * 16 + c * 4;
            Qt[(d + 0) * 64 + li] = v.x;
            Qt[(d + 1) * 64 + li] = v.y;
            Qt[(d + 2) * 64 + li] = v.z;
            Qt[(d + 3) * 64 + li] = v.w;
        }
    }

    float O[4][4];
    float m[4], l[4];
#pragma unroll
    for (int i = 0; i < 4; i++) {
        m[i] = NEG_INF; l[i] = 0.f;
#pragma unroll
        for (int j = 0; j < 4; j++) O[i][j] = 0.f;
    }

    for (int kt = 0; kt <= qb; kt++) {
        __syncthreads();
        {
            const float* kr = qkv + base + (size_t)(kt * 64 + li) * D3 + D_MODEL + q4 * 16;
#pragma unroll
            for (int c = 0; c < 4; c++) {
                int d = q4 * 16 + c * 4;
                float4 kv = *reinterpret_cast<const float4*>(kr + c * 4);
                KPt[(d + 0) * 64 + li] = kv.x;
                KPt[(d + 1) * 64 + li] = kv.y;
                KPt[(d + 2) * 64 + li] = kv.z;
                KPt[(d + 3) * 64 + li] = kv.w;
                float4 vv = *reinterpret_cast<const float4*>(kr + D_MODEL + c * 4);
                int pc = (d >> 2) ^ (li & 15);
                *reinterpret_cast<float4*>(&Vs[li * 64 + pc * 4]) = vv;
            }
        }
        __syncthreads();

        float s[4][4];
#pragma unroll
        for (int i = 0; i < 4; i++)
#pragma unroll
            for (int j = 0; j < 4; j++) s[i][j] = 0.f;

#pragma unroll 8
        for (int d = 0; d < 64; d++) {
            float4 av = *reinterpret_cast<const float4*>(&Qt[d * 64 + ty]);
            float4 bv = *reinterpret_cast<const float4*>(&KPt[d * 64 + tx]);
            float ra[4] = {av.x, av.y, av.z, av.w};
            float rb[4] = {bv.x, bv.y, bv.z, bv.w};
#pragma unroll
            for (int i = 0; i < 4; i++)
#pragma unroll
                for (int j = 0; j < 4; j++)
                    s[i][j] += ra[i] * rb[j];
        }

        const bool diag = (kt == qb);
        float corr[4];
#pragma unroll
        for (int i = 0; i < 4; i++) {
#pragma unroll
            for (int j = 0; j < 4; j++) {
                float v = s[i][j] * 0.125f;
                if (diag && (tx + j) > (ty + i)) v = NEG_INF;
                s[i][j] = v;
            }
            float mm = fmaxf(fmaxf(s[i][0], s[i][1]), fmaxf(s[i][2], s[i][3]));
            mm = fmaxf(mm, __shfl_xor_sync(0xffffffffu, mm, 1));
            mm = fmaxf(mm, __shfl_xor_sync(0xffffffffu, mm, 2));
            mm = fmaxf(mm, __shfl_xor_sync(0xffffffffu, mm, 4));
            mm = fmaxf(mm, __shfl_xor_sync(0xffffffffu, mm, 8));
            float nm = fmaxf(mm, m[i]);
            corr[i] = __expf(m[i] - nm);
            m[i] = nm;
            float ps = 0.f;
#pragma unroll
            for (int j = 0; j < 4; j++) {
                float p = __expf(s[i][j] - nm);
                s[i][j] = p;
                ps += p;
            }
            ps += __shfl_xor_sync(0xffffffffu, ps, 1);
            ps += __shfl_xor_sync(0xffffffffu, ps, 2);
            ps += __shfl_xor_sync(0xffffffffu, ps, 4);
            ps += __shfl_xor_sync(0xffffffffu, ps, 8);
            l[i] = l[i] * corr[i] + ps;
#pragma unroll
            for (int j = 0; j < 4; j++) O[i][j] *= corr[i];
        }

        __syncthreads();

#pragma unroll
        for (int j = 0; j < 4; j++) {
            int row = tx + j;
            int pc = (ty >> 2) ^ (row & 15);
            *reinterpret_cast<float4*>(&KPt[row * 64 + pc * 4]) =
                make_float4(s[0][j], s[1][j], s[2][j], s[3][j]);
        }
        __syncthreads();

#pragma unroll 8
        for (int k = 0; k < 64; k++) {
            int pa = (ty >> 2) ^ (k & 15);
            float4 av = *reinterpret_cast<const float4*>(&KPt[k * 64 + pa * 4]);
            int pb = (tx >> 2) ^ (k & 15);
            float4 bv = *reinterpret_cast<const float4*>(&Vs[k * 64 + pb * 4]);
            float ra[4] = {av.x, av.y, av.z, av.w};
            float rb[4] = {bv.x, bv.y, bv.z, bv.w};
#pragma unroll
            for (int i = 0; i < 4; i++)
#pragma unroll
                for (int j = 0; j < 4; j++)
                    O[i][j] += ra[i] * rb[j];
        }
    }

#pragma unroll
    for (int i = 0; i < 4; i++) {
        float inv = 1.f / l[i];
        float* orow = attn_out + (size_t)(b * SEQ + qb * 64 + ty + i) * D_MODEL + h * DH + tx;
        *reinterpret_cast<float4*>(orow) =
            make_float4(O[i][0] * inv, O[i][1] * inv, O[i][2] * inv, O[i][3] * inv);
    }
}

// ---------------------------------------------------------------------------
extern "C" void kernel_launch(void* const* d_in, const int* in_sizes, int n_in,
                              void* d_out, int out_size)
{
    const float* x     = (const float*)d_in[0];
    const float* W_in  = (const float*)d_in[1];
    const float* W_out = (const float*)d_in[2];
    float* out = (float*)d_out;

    float *qkv_buf, *attn_buf;
    __nv_bfloat16 *ah, *al, *bh, *bl;
    cudaGetSymbolAddress((void**)&qkv_buf, g_qkv);
    cudaGetSymbolAddress((void**)&attn_buf, g_attn);
    cudaGetSymbolAddress((void**)&ah, g_ah);
    cudaGetSymbolAddress((void**)&al, g_al);
    cudaGetSymbolAddress((void**)&bh, g_bh);
    cudaGetSymbolAddress((void**)&bl, g_bl);

    cudaFuncSetAttribute(gemm_mma, cudaFuncAttributeMaxDynamicSharedMemorySize, GEMM_SMEM);

    {   // split x -> bf16 hi/lo
        int n4 = MTOT * D_MODEL / 4;
        split_kernel<<<(n4 + 255) / 256, 256>>>(x, ah, al, n4);
    }
    {   // W_in -> [3072,1024] hi/lo
        dim3 grid(D3 / 32, D_MODEL / 32);
        transpose_split_kernel<<<grid, dim3(32, 8)>>>(W_in, bh, bl, D_MODEL, D3);
    }
    {   // qkv = x @ W_in
        dim3 grid(D3 / 128, MTOT / 128);
        gemm_mma<<<grid, 256, GEMM_SMEM>>>(ah, al, bh, bl, qkv_buf, MTOT, D3, D_MODEL);
    }
    {   // causal MHA
        dim3 grid(SEQ / 64, NHEAD, BATCH);
        attn_kernel<<<grid, 256>>>(qkv_buf, attn_buf);
    }
    {   // split attn
        int n4 = MTOT * D_MODEL / 4;
        split_kernel<<<(n4 + 255) / 256, 256>>>(attn_buf, ah, al, n4);
    }
    {   // W_out -> [1024,1024] hi/lo
        dim3 grid(D_MODEL / 32, D_MODEL / 32);
        transpose_split_kernel<<<grid, dim3(32, 8)>>>(W_out, bh, bl, D_MODEL, D_MODEL);
    }
    {   // out = attn @ W_out
        dim3 grid(D_MODEL / 128, MTOT / 128);
        gemm_mma<<<grid, 256, GEMM_SMEM>>>(ah, al, bh, bl, out, MTOT, D_MODEL, D_MODEL);
    }
}

// round 5
// speedup vs baseline: 1.5892x; 1.5892x over previous
#include <cuda_runtime.h>
#include <cuda_bf16.h>
#include <math.h>
#include <stdint.h>

#define D_MODEL 1024
#define SEQ     2048
#define BATCH   2
#define NHEAD   16
#define DH      64
#define D3      (3 * D_MODEL)
#define MTOT    (BATCH * SEQ)

__device__ float g_qkv[BATCH * SEQ * D3];
__device__ float g_attn[BATCH * SEQ * D_MODEL];

#define NEG_INF __int_as_float(0xff800000)

// ---------------- helpers ----------------
__device__ __forceinline__ uint32_t smem_u32(const void* p) {
    uint32_t a;
    asm("{ .reg .u64 t; cvta.to.shared.u64 t, %1; cvt.u32.u64 %0, t; }" : "=r"(a) : "l"(p));
    return a;
}
__device__ __forceinline__ void ldsm_x4(uint32_t* r, uint32_t addr) {
    asm volatile("ldmatrix.sync.aligned.m8n8.x4.shared.b16 {%0,%1,%2,%3}, [%4];"
                 : "=r"(r[0]), "=r"(r[1]), "=r"(r[2]), "=r"(r[3]) : "r"(addr));
}
__device__ __forceinline__ void ldsm_x4_t(uint32_t* r, uint32_t addr) {
    asm volatile("ldmatrix.sync.aligned.m8n8.x4.trans.shared.b16 {%0,%1,%2,%3}, [%4];"
                 : "=r"(r[0]), "=r"(r[1]), "=r"(r[2]), "=r"(r[3]) : "r"(addr));
}
__device__ __forceinline__ void mma16816(float* d, const uint32_t* a, uint32_t b0, uint32_t b1) {
    asm volatile("mma.sync.aligned.m16n8k16.row.col.f32.bf16.bf16.f32 "
                 "{%0,%1,%2,%3}, {%4,%5,%6,%7}, {%8,%9}, {%0,%1,%2,%3};"
                 : "+f"(d[0]), "+f"(d[1]), "+f"(d[2]), "+f"(d[3])
                 : "r"(a[0]), "r"(a[1]), "r"(a[2]), "r"(a[3]), "r"(b0), "r"(b1));
}
__device__ __forceinline__ uint32_t bf2pack(float a, float b) {
    __nv_bfloat162 t = __floats2bfloat162_rn(a, b);
    return *reinterpret_cast<uint32_t*>(&t);
}
__device__ __forceinline__ void split1(float v, float& hf, float& lf) {
    __nv_bfloat16 h = __float2bfloat16_rn(v);
    hf = __bfloat162float(h);
    lf = v - hf;
}

// ---------------------------------------------------------------------------
// fp32 SGEMM (measured 691/230 us) — unchanged from R2
// ---------------------------------------------------------------------------
__global__ __launch_bounds__(256) void sgemm_kernel(
    const float* __restrict__ A, const float* __restrict__ B,
    float* __restrict__ C, int M, int N, int K)
{
    constexpr int BM = 128, BN = 128, BK = 8, TM = 8, TN = 8;
    __shared__ float As[BK][BM];
    __shared__ float Bs[BK][BN];

    const int tid  = threadIdx.x;
    const int cRow = blockIdx.y * BM;
    const int cCol = blockIdx.x * BN;

    const int aRow = tid >> 1;
    const int aCol = (tid & 1) * 4;
    const int bRow = tid >> 5;
    const int bCol = (tid & 31) * 4;

    const int ty = (tid >> 4) * TM;
    const int tx = (tid & 15) * TN;

    float acc[TM][TN];
#pragma unroll
    for (int i = 0; i < TM; i++)
#pragma unroll
        for (int j = 0; j < TN; j++) acc[i][j] = 0.f;

    const float* Aptr = A + (cRow + aRow) * K + aCol;
    const float* Bptr = B + bRow * N + cCol + bCol;

    for (int k0 = 0; k0 < K; k0 += BK) {
        float4 av = *reinterpret_cast<const float4*>(Aptr + k0);
        float4 bv = *reinterpret_cast<const float4*>(Bptr + (size_t)k0 * N);
        As[aCol + 0][aRow] = av.x;
        As[aCol + 1][aRow] = av.y;
        As[aCol + 2][aRow] = av.z;
        As[aCol + 3][aRow] = av.w;
        *reinterpret_cast<float4*>(&Bs[bRow][bCol]) = bv;
        __syncthreads();

#pragma unroll
        for (int k = 0; k < BK; k++) {
            float4 a0 = *reinterpret_cast<const float4*>(&As[k][ty]);
            float4 a1 = *reinterpret_cast<const float4*>(&As[k][ty + 4]);
            float4 b0 = *reinterpret_cast<const float4*>(&Bs[k][tx]);
            float4 b1 = *reinterpret_cast<const float4*>(&Bs[k][tx + 4]);
            float ra[TM] = {a0.x, a0.y, a0.z, a0.w, a1.x, a1.y, a1.z, a1.w};
            float rb[TN] = {b0.x, b0.y, b0.z, b0.w, b1.x, b1.y, b1.z, b1.w};
#pragma unroll
            for (int i = 0; i < TM; i++)
#pragma unroll
                for (int j = 0; j < TN; j++)
                    acc[i][j] += ra[i] * rb[j];
        }
        __syncthreads();
    }

#pragma unroll
    for (int i = 0; i < TM; i++) {
        float* crow = C + (size_t)(cRow + ty + i) * N + cCol + tx;
        *reinterpret_cast<float4*>(crow)     = make_float4(acc[i][0], acc[i][1], acc[i][2], acc[i][3]);
        *reinterpret_cast<float4*>(crow + 4) = make_float4(acc[i][4], acc[i][5], acc[i][6], acc[i][7]);
    }
}

// ---------------------------------------------------------------------------
// Flash attention with mma.sync bf16 3-split (QK and PV).
// Block = 128 q rows x (head,batch), 256 threads, 8 warps x 16-row strips.
// K/V tiles 64x64: fp32 register-staged -> hi/lo bf16 smem (stride 72).
// ---------------------------------------------------------------------------
#define KVSTRIDE 72

__global__ __launch_bounds__(256) void attn_mma_kernel(
    const float* __restrict__ qkv, float* __restrict__ attn_out)
{
    __shared__ __nv_bfloat16 Kh[64 * KVSTRIDE], Kl[64 * KVSTRIDE];
    __shared__ __nv_bfloat16 Vh[64 * KVSTRIDE], Vl[64 * KVSTRIDE];

    const int bx = blockIdx.x;          // q block (128 rows)
    const int h  = blockIdx.y;
    const int b  = blockIdx.z;
    const int tid = threadIdx.x, lane = tid & 31, warp = tid >> 5;
    const int qr0 = bx * 128;
    const size_t base = (size_t)(b * SEQ) * D3 + h * DH;

    const int tg = lane >> 3, tr = lane & 7;
    const int ar  = ((tg & 1) << 3) + tr,  acs = (tg >> 1) << 3;  // A / trans pattern
    const int br  = ((tg >> 1) << 3) + tr, bcs = (tg & 1) << 3;   // B pattern

    const uint32_t sKh = smem_u32(Kh), sKl = smem_u32(Kl);
    const uint32_t sVh = smem_u32(Vh), sVl = smem_u32(Vl);

    // ---- stage Q into smem (hi->Kh/Vh, lo->Kl/Vl), build register frags ----
    {
        const int row = tid >> 1, cs = (tid & 1) * 32;
        const float* qp = qkv + base + (size_t)(qr0 + row) * D3 + cs;
        float qv[32];
#pragma unroll
        for (int i = 0; i < 8; i++) {
            float4 v = *reinterpret_cast<const float4*>(qp + i * 4);
            qv[4*i] = v.x; qv[4*i+1] = v.y; qv[4*i+2] = v.z; qv[4*i+3] = v.w;
        }
        uint32_t* hp = reinterpret_cast<uint32_t*>((row < 64 ? Kh : Vh) + (row & 63) * KVSTRIDE + cs);
        uint32_t* lp = reinterpret_cast<uint32_t*>((row < 64 ? Kl : Vl) + (row & 63) * KVSTRIDE + cs);
#pragma unroll
        for (int e = 0; e < 16; e++) {
            float h0, l0, h1, l1;
            split1(qv[2*e], h0, l0); split1(qv[2*e+1], h1, l1);
            hp[e] = bf2pack(h0, h1);
            lp[e] = bf2pack(l0, l1);
        }
    }
    __syncthreads();

    uint32_t qh[4][4], ql[4][4];
    {
        const uint32_t hb = (warp < 4) ? sKh : sVh;
        const uint32_t lb = (warp < 4) ? sKl : sVl;
        const int strip = (warp & 3) * 16;
#pragma unroll
        for (int kc = 0; kc < 4; kc++) {
            uint32_t off = (uint32_t)((strip + ar) * KVSTRIDE + kc * 16 + acs) * 2;
            ldsm_x4(qh[kc], hb + off);
            ldsm_x4(ql[kc], lb + off);
        }
    }
    __syncthreads();   // Q frag reads done; smem free for K/V

    float O[8][4];
#pragma unroll
    for (int j = 0; j < 8; j++)
#pragma unroll
        for (int c = 0; c < 4; c++) O[j][c] = 0.f;
    float m0 = NEG_INF, m1 = NEG_INF, l0 = 0.f, l1 = 0.f;

    const int ntiles = 2 * bx + 2;
    const int lrow = tid >> 2, lcs = (tid & 3) * 16;   // loader mapping
    float kbuf[16], vbuf[16];

    auto load_kv = [&](int kt) {
        const float* p = qkv + base + (size_t)(kt * 64 + lrow) * D3 + D_MODEL + lcs;
#pragma unroll
        for (int i = 0; i < 4; i++) {
            float4 v = *reinterpret_cast<const float4*>(p + i * 4);
            kbuf[4*i] = v.x; kbuf[4*i+1] = v.y; kbuf[4*i+2] = v.z; kbuf[4*i+3] = v.w;
            float4 w = *reinterpret_cast<const float4*>(p + D_MODEL + i * 4);
            vbuf[4*i] = w.x; vbuf[4*i+1] = w.y; vbuf[4*i+2] = w.z; vbuf[4*i+3] = w.w;
        }
    };
    load_kv(0);

    const float SC = 0.125f * 1.4426950408889634f;   // 1/sqrt(64) * log2(e)
    const int wrow = warp * 16 + (lane >> 2);
    const int row0g = qr0 + wrow, row1g = row0g + 8;

    for (int kt = 0; kt < ntiles; kt++) {
        // convert staged fp32 -> hi/lo bf16 smem
        {
            uint32_t* kh = reinterpret_cast<uint32_t*>(Kh + lrow * KVSTRIDE + lcs);
            uint32_t* kl = reinterpret_cast<uint32_t*>(Kl + lrow * KVSTRIDE + lcs);
            uint32_t* vh = reinterpret_cast<uint32_t*>(Vh + lrow * KVSTRIDE + lcs);
            uint32_t* vl = reinterpret_cast<uint32_t*>(Vl + lrow * KVSTRIDE + lcs);
#pragma unroll
            for (int e = 0; e < 8; e++) {
                float h0, lo0, h1, lo1;
                split1(kbuf[2*e], h0, lo0); split1(kbuf[2*e+1], h1, lo1);
                kh[e] = bf2pack(h0, h1); kl[e] = bf2pack(lo0, lo1);
                split1(vbuf[2*e], h0, lo0); split1(vbuf[2*e+1], h1, lo1);
                vh[e] = bf2pack(h0, h1); vl[e] = bf2pack(lo0, lo1);
            }
        }
        __syncthreads();
        if (kt + 1 < ntiles) load_kv(kt + 1);

        // ---- S = Q K^T  (3-pass bf16) ----
        float sc[8][4];
#pragma unroll
        for (int j = 0; j < 8; j++)
#pragma unroll
            for (int c = 0; c < 4; c++) sc[j][c] = 0.f;

#pragma unroll
        for (int kc = 0; kc < 4; kc++) {
#pragma unroll
            for (int n16 = 0; n16 < 4; n16++) {
                uint32_t off = (uint32_t)((n16 * 16 + br) * KVSTRIDE + kc * 16 + bcs) * 2;
                uint32_t kh4[4], kl4[4];
                ldsm_x4(kh4, sKh + off);
                ldsm_x4(kl4, sKl + off);
                mma16816(sc[2*n16],   qh[kc], kh4[0], kh4[1]);
                mma16816(sc[2*n16+1], qh[kc], kh4[2], kh4[3]);
                mma16816(sc[2*n16],   qh[kc], kl4[0], kl4[1]);
                mma16816(sc[2*n16+1], qh[kc], kl4[2], kl4[3]);
                mma16816(sc[2*n16],   ql[kc], kh4[0], kh4[1]);
                mma16816(sc[2*n16+1], ql[kc], kh4[2], kh4[3]);
            }
        }

        // ---- online softmax (base-2 domain) ----
        const bool need_mask = (kt >= 2 * bx);
        float mx0 = -1e30f, mx1 = -1e30f;
#pragma unroll
        for (int f = 0; f < 8; f++) {
            const int colb = kt * 64 + f * 8 + ((lane & 3) << 1);
#pragma unroll
            for (int c = 0; c < 4; c++) {
                float t = sc[f][c] * SC;
                if (need_mask) {
                    int col = colb + (c & 1);
                    int row = (c < 2) ? row0g : row1g;
                    if (col > row) t = -1e30f;
                }
                sc[f][c] = t;
            }
            mx0 = fmaxf(mx0, fmaxf(sc[f][0], sc[f][1]));
            mx1 = fmaxf(mx1, fmaxf(sc[f][2], sc[f][3]));
        }
        mx0 = fmaxf(mx0, __shfl_xor_sync(0xffffffffu, mx0, 1));
        mx0 = fmaxf(mx0, __shfl_xor_sync(0xffffffffu, mx0, 2));
        mx1 = fmaxf(mx1, __shfl_xor_sync(0xffffffffu, mx1, 1));
        mx1 = fmaxf(mx1, __shfl_xor_sync(0xffffffffu, mx1, 2));

        const float nm0 = fmaxf(m0, mx0), nm1 = fmaxf(m1, mx1);
        const float corr0 = exp2f(m0 - nm0), corr1 = exp2f(m1 - nm1);
        m0 = nm0; m1 = nm1;

        float s0 = 0.f, s1 = 0.f;
#pragma unroll
        for (int f = 0; f < 8; f++) {
            float p0 = exp2f(sc[f][0] - nm0);
            float p1 = exp2f(sc[f][1] - nm0);
            float p2 = exp2f(sc[f][2] - nm1);
            float p3 = exp2f(sc[f][3] - nm1);
            sc[f][0] = p0; sc[f][1] = p1; sc[f][2] = p2; sc[f][3] = p3;
            s0 += p0 + p1; s1 += p2 + p3;
        }
        s0 += __shfl_xor_sync(0xffffffffu, s0, 1);
        s0 += __shfl_xor_sync(0xffffffffu, s0, 2);
        s1 += __shfl_xor_sync(0xffffffffu, s1, 1);
        s1 += __shfl_xor_sync(0xffffffffu, s1, 2);
        l0 = l0 * corr0 + s0;
        l1 = l1 * corr1 + s1;
#pragma unroll
        for (int j = 0; j < 8; j++) {
            O[j][0] *= corr0; O[j][1] *= corr0;
            O[j][2] *= corr1; O[j][3] *= corr1;
        }

        // ---- pack P into hi/lo A-fragments (C->A layout identity) ----
        uint32_t pfh[4][4], pfl[4][4];
#pragma unroll
        for (int kc = 0; kc < 4; kc++) {
#pragma unroll
            for (int half = 0; half < 2; half++) {
                const int f = 2 * kc + half;
                float h0, lo0, h1, lo1, h2, lo2, h3, lo3;
                split1(sc[f][0], h0, lo0); split1(sc[f][1], h1, lo1);
                split1(sc[f][2], h2, lo2); split1(sc[f][3], h3, lo3);
                pfh[kc][2*half]   = bf2pack(h0, h1);
                pfh[kc][2*half+1] = bf2pack(h2, h3);
                pfl[kc][2*half]   = bf2pack(lo0, lo1);
                pfl[kc][2*half+1] = bf2pack(lo2, lo3);
            }
        }

        // ---- O += P V  (3-pass bf16, V via ldmatrix.trans) ----
#pragma unroll
        for (int kc = 0; kc < 4; kc++) {
#pragma unroll
            for (int n16 = 0; n16 < 4; n16++) {
                uint32_t off = (uint32_t)((kc * 16 + ar) * KVSTRIDE + n16 * 16 + acs) * 2;
                uint32_t vh4[4], vl4[4];
                ldsm_x4_t(vh4, sVh + off);
                ldsm_x4_t(vl4, sVl + off);
                mma16816(O[2*n16],   pfh[kc], vh4[0], vh4[1]);
                mma16816(O[2*n16+1], pfh[kc], vh4[2], vh4[3]);
                mma16816(O[2*n16],   pfh[kc], vl4[0], vl4[1]);
                mma16816(O[2*n16+1], pfh[kc], vl4[2], vl4[3]);
                mma16816(O[2*n16],   pfl[kc], vh4[0], vh4[1]);
                mma16816(O[2*n16+1], pfl[kc], vh4[2], vh4[3]);
            }
        }
        __syncthreads();   // done reading smem; next convert may overwrite
    }

    // ---- epilogue ----
    const float inv0 = 1.f / l0, inv1 = 1.f / l1;
    float* o0 = attn_out + (size_t)(b * SEQ + row0g) * D_MODEL + h * DH;
    float* o1 = attn_out + (size_t)(b * SEQ + row1g) * D_MODEL + h * DH;
    const int ec = (lane & 3) << 1;
#pragma unroll
    for (int j = 0; j < 8; j++) {
        *reinterpret_cast<float2*>(o0 + j * 8 + ec) = make_float2(O[j][0] * inv0, O[j][1] * inv0);
        *reinterpret_cast<float2*>(o1 + j * 8 + ec) = make_float2(O[j][2] * inv1, O[j][3] * inv1);
    }
}

// ---------------------------------------------------------------------------
extern "C" void kernel_launch(void* const* d_in, const int* in_sizes, int n_in,
                              void* d_out, int out_size)
{
    const float* x     = (const float*)d_in[0];
    const float* W_in  = (const float*)d_in[1];
    const float* W_out = (const float*)d_in[2];
    float* out = (float*)d_out;

    float *qkv_buf, *attn_buf;
    cudaGetSymbolAddress((void**)&qkv_buf, g_qkv);
    cudaGetSymbolAddress((void**)&attn_buf, g_attn);

    {   // qkv = x @ W_in
        dim3 grid(D3 / 128, MTOT / 128);
        sgemm_kernel<<<grid, 256>>>(x, W_in, qkv_buf, MTOT, D3, D_MODEL);
    }
    {   // causal MHA (mma.sync bf16x3 flash)
        dim3 grid(SEQ / 128, NHEAD, BATCH);
        attn_mma_kernel<<<grid, 256>>>(qkv_buf, attn_buf);
    }
    {   // out = attn @ W_out
        dim3 grid(D_MODEL / 128, MTOT / 128);
        sgemm_kernel<<<grid, 256>>>(attn_buf, W_out, out, MTOT, D_MODEL, D_MODEL);
    }
}

// round 6
// speedup vs baseline: 2.7001x; 1.6990x over previous
#include <cuda_runtime.h>
#include <cuda_bf16.h>
#include <math.h>
#include <stdint.h>

#define D_MODEL 1024
#define SEQ     2048
#define BATCH   2
#define NHEAD   16
#define DH      64
#define D3      (3 * D_MODEL)
#define MTOT    (BATCH * SEQ)

__device__ float g_qkv[BATCH * SEQ * D3];
__device__ __nv_bfloat16 g_ah[MTOT * D_MODEL];
__device__ __nv_bfloat16 g_al[MTOT * D_MODEL];
__device__ __nv_bfloat16 g_bh[D3 * D_MODEL];
__device__ __nv_bfloat16 g_bl[D3 * D_MODEL];

#define NEG_INF __int_as_float(0xff800000)

// ---------------- helpers ----------------
__device__ __forceinline__ uint32_t smem_u32(const void* p) {
    uint32_t a;
    asm("{ .reg .u64 t; cvta.to.shared.u64 t, %1; cvt.u32.u64 %0, t; }" : "=r"(a) : "l"(p));
    return a;
}
__device__ __forceinline__ void ldsm_x4(uint32_t* r, uint32_t addr) {
    asm volatile("ldmatrix.sync.aligned.m8n8.x4.shared.b16 {%0,%1,%2,%3}, [%4];"
                 : "=r"(r[0]), "=r"(r[1]), "=r"(r[2]), "=r"(r[3]) : "r"(addr));
}
__device__ __forceinline__ void ldsm_x4_t(uint32_t* r, uint32_t addr) {
    asm volatile("ldmatrix.sync.aligned.m8n8.x4.trans.shared.b16 {%0,%1,%2,%3}, [%4];"
                 : "=r"(r[0]), "=r"(r[1]), "=r"(r[2]), "=r"(r[3]) : "r"(addr));
}
__device__ __forceinline__ void mma16816(float* d, const uint32_t* a, uint32_t b0, uint32_t b1) {
    asm volatile("mma.sync.aligned.m16n8k16.row.col.f32.bf16.bf16.f32 "
                 "{%0,%1,%2,%3}, {%4,%5,%6,%7}, {%8,%9}, {%0,%1,%2,%3};"
                 : "+f"(d[0]), "+f"(d[1]), "+f"(d[2]), "+f"(d[3])
                 : "r"(a[0]), "r"(a[1]), "r"(a[2]), "r"(a[3]), "r"(b0), "r"(b1));
}
__device__ __forceinline__ uint32_t bf2pack(float a, float b) {
    __nv_bfloat162 t = __floats2bfloat162_rn(a, b);
    return *reinterpret_cast<uint32_t*>(&t);
}
__device__ __forceinline__ void split1(float v, float& hf, float& lf) {
    __nv_bfloat16 h = __float2bfloat16_rn(v);
    hf = __bfloat162float(h);
    lf = v - hf;
}

// ---------------- conversion kernels ----------------
__global__ void split_kernel(const float* __restrict__ in,
                             __nv_bfloat16* __restrict__ hi,
                             __nv_bfloat16* __restrict__ lo, int n4)
{
    int i = blockIdx.x * blockDim.x + threadIdx.x;
    if (i >= n4) return;
    float4 v = reinterpret_cast<const float4*>(in)[i];
    float f[4] = {v.x, v.y, v.z, v.w};
    float h[4], l[4];
#pragma unroll
    for (int j = 0; j < 4; j++) split1(f[j], h[j], l[j]);
    reinterpret_cast<uint32_t*>(hi)[2*i]   = bf2pack(h[0], h[1]);
    reinterpret_cast<uint32_t*>(hi)[2*i+1] = bf2pack(h[2], h[3]);
    reinterpret_cast<uint32_t*>(lo)[2*i]   = bf2pack(l[0], l[1]);
    reinterpret_cast<uint32_t*>(lo)[2*i+1] = bf2pack(l[2], l[3]);
}

__global__ void transpose_split_kernel(const float* __restrict__ W,
                                       __nv_bfloat16* __restrict__ th,
                                       __nv_bfloat16* __restrict__ tl,
                                       int K, int N)
{
    __shared__ float t[32][33];
    int k0 = blockIdx.y * 32, n0 = blockIdx.x * 32;
    int tx = threadIdx.x, ty = threadIdx.y;
#pragma unroll
    for (int r = 0; r < 4; r++) {
        int row = ty + r * 8;
        t[row][tx] = W[(size_t)(k0 + row) * N + n0 + tx];
    }
    __syncthreads();
#pragma unroll
    for (int r = 0; r < 4; r++) {
        int nn = ty + r * 8;
        float v = t[tx][nn], h, l;
        split1(v, h, l);
        size_t o = (size_t)(n0 + nn) * K + k0 + tx;
        th[o] = __float2bfloat16_rn(h);
        tl[o] = __float2bfloat16_rn(l);
    }
}

// ---------------------------------------------------------------------------
// HMMA bf16x3 GEMM: C fp32 = (Ah+Al)[M,K] x (Bh+Bl)[N,K]^T  (drop Al*Bl)
// 256 thr, 128x128 tile, BK=32, double-buffered smem, register-staged LDG.
// ---------------------------------------------------------------------------
#define ROWP 40
#define TILE_ELEMS (128 * ROWP)
#define TILE_BYTES (TILE_ELEMS * 2)
#define GEMM_SMEM (2 * 4 * TILE_BYTES)   // 81920

__global__ __launch_bounds__(256) void gemm_hmma(
    const __nv_bfloat16* __restrict__ Ah, const __nv_bfloat16* __restrict__ Al,
    const __nv_bfloat16* __restrict__ Bh, const __nv_bfloat16* __restrict__ Bl,
    float* __restrict__ C, int M, int N, int K)
{
    extern __shared__ __nv_bfloat16 sm[];
    const uint32_t sb = smem_u32(sm);
    const int tid = threadIdx.x, lane = tid & 31, warp = tid >> 5;
    const int wm = warp & 1, wn = warp >> 1;
    const int cRow = blockIdx.y * 128, cCol = blockIdx.x * 128;
    const int KSTEPS = K / 32;

    const int tg = lane >> 3, tr = lane & 7;
    const int a_row = ((tg & 1) << 3) + tr, a_col = (tg >> 1) << 3;
    const int b_row = ((tg >> 1) << 3) + tr, b_col = (tg & 1) << 3;

    const int lrow = tid >> 2, lcc = (tid & 3) * 8;   // loader: 4 threads/row

    float acc[4][4][4];
#pragma unroll
    for (int i = 0; i < 4; i++)
#pragma unroll
        for (int j = 0; j < 4; j++)
#pragma unroll
            for (int c = 0; c < 4; c++) acc[i][j][c] = 0.f;

    uint4 stg[4][2];
    auto ldg_stage = [&](int k0) {
        const __nv_bfloat16* srcs[4] = {Ah, Al, Bh, Bl};
#pragma unroll
        for (int t = 0; t < 4; t++) {
            const int r0 = (t < 2) ? cRow : cCol;
#pragma unroll
            for (int i = 0; i < 2; i++) {
                const int row = (i << 6) + lrow;
                stg[t][i] = *reinterpret_cast<const uint4*>(
                    srcs[t] + (size_t)(r0 + row) * K + k0 + lcc);
            }
        }
    };
    auto sts_stage = [&](int s) {
#pragma unroll
        for (int t = 0; t < 4; t++)
#pragma unroll
            for (int i = 0; i < 2; i++) {
                const int row = (i << 6) + lrow;
                *reinterpret_cast<uint4*>(&sm[(s * 4 + t) * TILE_ELEMS + row * ROWP + lcc]) = stg[t][i];
            }
    };

    ldg_stage(0);
    sts_stage(0);
    __syncthreads();

    for (int ks = 0; ks < KSTEPS; ks++) {
        if (ks + 1 < KSTEPS) ldg_stage((ks + 1) * 32);

        const int s = ks & 1;
        const uint32_t stb = sb + s * 4 * TILE_BYTES;
#pragma unroll
        for (int k16 = 0; k16 < 2; k16++) {
            const int kc = k16 * 16;
            uint32_t ah[4][4], al[4][4];
#pragma unroll
            for (int mi = 0; mi < 4; mi++) {
                const int row = wm * 64 + mi * 16 + a_row;
                const uint32_t off = (uint32_t)(row * ROWP + kc + a_col) * 2;
                ldsm_x4(ah[mi], stb + off);
                ldsm_x4(al[mi], stb + TILE_BYTES + off);
            }
#pragma unroll
            for (int p = 0; p < 2; p++) {
                const int row = wn * 32 + p * 16 + b_row;
                const uint32_t off = (uint32_t)(row * ROWP + kc + b_col) * 2;
                uint32_t rh[4], rl[4];
                ldsm_x4(rh, stb + 2 * TILE_BYTES + off);
                ldsm_x4(rl, stb + 3 * TILE_BYTES + off);
#pragma unroll
                for (int mi = 0; mi < 4; mi++) {
                    mma16816(acc[mi][2*p],   ah[mi], rh[0], rh[1]);
                    mma16816(acc[mi][2*p+1], ah[mi], rh[2], rh[3]);
                    mma16816(acc[mi][2*p],   ah[mi], rl[0], rl[1]);
                    mma16816(acc[mi][2*p+1], ah[mi], rl[2], rl[3]);
                    mma16816(acc[mi][2*p],   al[mi], rh[0], rh[1]);
                    mma16816(acc[mi][2*p+1], al[mi], rh[2], rh[3]);
                }
            }
        }
        __syncthreads();
        if (ks + 1 < KSTEPS) {
            sts_stage(s ^ 1);
            __syncthreads();
        }
    }

    const int er = lane >> 2, ec = (lane & 3) * 2;
#pragma unroll
    for (int mi = 0; mi < 4; mi++) {
#pragma unroll
        for (int ni = 0; ni < 4; ni++) {
            const int row = cRow + wm * 64 + mi * 16 + er;
            const int col = cCol + wn * 32 + ni * 8 + ec;
            *reinterpret_cast<float2*>(C + (size_t)row * N + col) =
                make_float2(acc[mi][ni][0], acc[mi][ni][1]);
            *reinterpret_cast<float2*>(C + (size_t)(row + 8) * N + col) =
                make_float2(acc[mi][ni][2], acc[mi][ni][3]);
        }
    }
}

// ---------------------------------------------------------------------------
// Flash attention, mma.sync bf16x3 (from R5), epilogue emits hi/lo bf16.
// ---------------------------------------------------------------------------
#define KVSTRIDE 72

__global__ __launch_bounds__(256) void attn_mma_kernel(
    const float* __restrict__ qkv,
    __nv_bfloat16* __restrict__ outh, __nv_bfloat16* __restrict__ outl)
{
    __shared__ __nv_bfloat16 Kh[64 * KVSTRIDE], Kl[64 * KVSTRIDE];
    __shared__ __nv_bfloat16 Vh[64 * KVSTRIDE], Vl[64 * KVSTRIDE];

    const int bx = blockIdx.x;
    const int h  = blockIdx.y;
    const int b  = blockIdx.z;
    const int tid = threadIdx.x, lane = tid & 31, warp = tid >> 5;
    const int qr0 = bx * 128;
    const size_t base = (size_t)(b * SEQ) * D3 + h * DH;

    const int tg = lane >> 3, tr = lane & 7;
    const int ar  = ((tg & 1) << 3) + tr,  acs = (tg >> 1) << 3;
    const int br  = ((tg >> 1) << 3) + tr, bcs = (tg & 1) << 3;

    const uint32_t sKh = smem_u32(Kh), sKl = smem_u32(Kl);
    const uint32_t sVh = smem_u32(Vh), sVl = smem_u32(Vl);

    {
        const int row = tid >> 1, cs = (tid & 1) * 32;
        const float* qp = qkv + base + (size_t)(qr0 + row) * D3 + cs;
        float qv[32];
#pragma unroll
        for (int i = 0; i < 8; i++) {
            float4 v = *reinterpret_cast<const float4*>(qp + i * 4);
            qv[4*i] = v.x; qv[4*i+1] = v.y; qv[4*i+2] = v.z; qv[4*i+3] = v.w;
        }
        uint32_t* hp = reinterpret_cast<uint32_t*>((row < 64 ? Kh : Vh) + (row & 63) * KVSTRIDE + cs);
        uint32_t* lp = reinterpret_cast<uint32_t*>((row < 64 ? Kl : Vl) + (row & 63) * KVSTRIDE + cs);
#pragma unroll
        for (int e = 0; e < 16; e++) {
            float h0, l0, h1, l1;
            split1(qv[2*e], h0, l0); split1(qv[2*e+1], h1, l1);
            hp[e] = bf2pack(h0, h1);
            lp[e] = bf2pack(l0, l1);
        }
    }
    __syncthreads();

    uint32_t qh[4][4], ql[4][4];
    {
        const uint32_t hb = (warp < 4) ? sKh : sVh;
        const uint32_t lb = (warp < 4) ? sKl : sVl;
        const int strip = (warp & 3) * 16;
#pragma unroll
        for (int kc = 0; kc < 4; kc++) {
            uint32_t off = (uint32_t)((strip + ar) * KVSTRIDE + kc * 16 + acs) * 2;
            ldsm_x4(qh[kc], hb + off);
            ldsm_x4(ql[kc], lb + off);
        }
    }
    __syncthreads();

    float O[8][4];
#pragma unroll
    for (int j = 0; j < 8; j++)
#pragma unroll
        for (int c = 0; c < 4; c++) O[j][c] = 0.f;
    float m0 = NEG_INF, m1 = NEG_INF, l0 = 0.f, l1 = 0.f;

    const int ntiles = 2 * bx + 2;
    const int lrow = tid >> 2, lcs = (tid & 3) * 16;
    float kbuf[16], vbuf[16];

    auto load_kv = [&](int kt) {
        const float* p = qkv + base + (size_t)(kt * 64 + lrow) * D3 + D_MODEL + lcs;
#pragma unroll
        for (int i = 0; i < 4; i++) {
            float4 v = *reinterpret_cast<const float4*>(p + i * 4);
            kbuf[4*i] = v.x; kbuf[4*i+1] = v.y; kbuf[4*i+2] = v.z; kbuf[4*i+3] = v.w;
            float4 w = *reinterpret_cast<const float4*>(p + D_MODEL + i * 4);
            vbuf[4*i] = w.x; vbuf[4*i+1] = w.y; vbuf[4*i+2] = w.z; vbuf[4*i+3] = w.w;
        }
    };
    load_kv(0);

    const float SC = 0.125f * 1.4426950408889634f;
    const int wrow = warp * 16 + (lane >> 2);
    const int row0g = qr0 + wrow, row1g = row0g + 8;

    for (int kt = 0; kt < ntiles; kt++) {
        {
            uint32_t* kh = reinterpret_cast<uint32_t*>(Kh + lrow * KVSTRIDE + lcs);
            uint32_t* kl = reinterpret_cast<uint32_t*>(Kl + lrow * KVSTRIDE + lcs);
            uint32_t* vh = reinterpret_cast<uint32_t*>(Vh + lrow * KVSTRIDE + lcs);
            uint32_t* vl = reinterpret_cast<uint32_t*>(Vl + lrow * KVSTRIDE + lcs);
#pragma unroll
            for (int e = 0; e < 8; e++) {
                float h0, lo0, h1, lo1;
                split1(kbuf[2*e], h0, lo0); split1(kbuf[2*e+1], h1, lo1);
                kh[e] = bf2pack(h0, h1); kl[e] = bf2pack(lo0, lo1);
                split1(vbuf[2*e], h0, lo0); split1(vbuf[2*e+1], h1, lo1);
                vh[e] = bf2pack(h0, h1); vl[e] = bf2pack(lo0, lo1);
            }
        }
        __syncthreads();
        if (kt + 1 < ntiles) load_kv(kt + 1);

        float sc[8][4];
#pragma unroll
        for (int j = 0; j < 8; j++)
#pragma unroll
            for (int c = 0; c < 4; c++) sc[j][c] = 0.f;

#pragma unroll
        for (int kc = 0; kc < 4; kc++) {
#pragma unroll
            for (int n16 = 0; n16 < 4; n16++) {
                uint32_t off = (uint32_t)((n16 * 16 + br) * KVSTRIDE + kc * 16 + bcs) * 2;
                uint32_t kh4[4], kl4[4];
                ldsm_x4(kh4, sKh + off);
                ldsm_x4(kl4, sKl + off);
                mma16816(sc[2*n16],   qh[kc], kh4[0], kh4[1]);
                mma16816(sc[2*n16+1], qh[kc], kh4[2], kh4[3]);
                mma16816(sc[2*n16],   qh[kc], kl4[0], kl4[1]);
                mma16816(sc[2*n16+1], qh[kc], kl4[2], kl4[3]);
                mma16816(sc[2*n16],   ql[kc], kh4[0], kh4[1]);
                mma16816(sc[2*n16+1], ql[kc], kh4[2], kh4[3]);
            }
        }

        const bool need_mask = (kt >= 2 * bx);
        float mx0 = -1e30f, mx1 = -1e30f;
#pragma unroll
        for (int f = 0; f < 8; f++) {
            const int colb = kt * 64 + f * 8 + ((lane & 3) << 1);
#pragma unroll
            for (int c = 0; c < 4; c++) {
                float t = sc[f][c] * SC;
                if (need_mask) {
                    int col = colb + (c & 1);
                    int row = (c < 2) ? row0g : row1g;
                    if (col > row) t = -1e30f;
                }
                sc[f][c] = t;
            }
            mx0 = fmaxf(mx0, fmaxf(sc[f][0], sc[f][1]));
            mx1 = fmaxf(mx1, fmaxf(sc[f][2], sc[f][3]));
        }
        mx0 = fmaxf(mx0, __shfl_xor_sync(0xffffffffu, mx0, 1));
        mx0 = fmaxf(mx0, __shfl_xor_sync(0xffffffffu, mx0, 2));
        mx1 = fmaxf(mx1, __shfl_xor_sync(0xffffffffu, mx1, 1));
        mx1 = fmaxf(mx1, __shfl_xor_sync(0xffffffffu, mx1, 2));

        const float nm0 = fmaxf(m0, mx0), nm1 = fmaxf(m1, mx1);
        const float corr0 = exp2f(m0 - nm0), corr1 = exp2f(m1 - nm1);
        m0 = nm0; m1 = nm1;

        float s0 = 0.f, s1 = 0.f;
#pragma unroll
        for (int f = 0; f < 8; f++) {
            float p0 = exp2f(sc[f][0] - nm0);
            float p1 = exp2f(sc[f][1] - nm0);
            float p2 = exp2f(sc[f][2] - nm1);
            float p3 = exp2f(sc[f][3] - nm1);
            sc[f][0] = p0; sc[f][1] = p1; sc[f][2] = p2; sc[f][3] = p3;
            s0 += p0 + p1; s1 += p2 + p3;
        }
        s0 += __shfl_xor_sync(0xffffffffu, s0, 1);
        s0 += __shfl_xor_sync(0xffffffffu, s0, 2);
        s1 += __shfl_xor_sync(0xffffffffu, s1, 1);
        s1 += __shfl_xor_sync(0xffffffffu, s1, 2);
        l0 = l0 * corr0 + s0;
        l1 = l1 * corr1 + s1;
#pragma unroll
        for (int j = 0; j < 8; j++) {
            O[j][0] *= corr0; O[j][1] *= corr0;
            O[j][2] *= corr1; O[j][3] *= corr1;
        }

        uint32_t pfh[4][4], pfl[4][4];
#pragma unroll
        for (int kc = 0; kc < 4; kc++) {
#pragma unroll
            for (int half = 0; half < 2; half++) {
                const int f = 2 * kc + half;
                float h0, lo0, h1, lo1, h2, lo2, h3, lo3;
                split1(sc[f][0], h0, lo0); split1(sc[f][1], h1, lo1);
                split1(sc[f][2], h2, lo2); split1(sc[f][3], h3, lo3);
                pfh[kc][2*half]   = bf2pack(h0, h1);
                pfh[kc][2*half+1] = bf2pack(h2, h3);
                pfl[kc][2*half]   = bf2pack(lo0, lo1);
                pfl[kc][2*half+1] = bf2pack(lo2, lo3);
            }
        }

#pragma unroll
        for (int kc = 0; kc < 4; kc++) {
#pragma unroll
            for (int n16 = 0; n16 < 4; n16++) {
                uint32_t off = (uint32_t)((kc * 16 + ar) * KVSTRIDE + n16 * 16 + acs) * 2;
                uint32_t vh4[4], vl4[4];
                ldsm_x4_t(vh4, sVh + off);
                ldsm_x4_t(vl4, sVl + off);
                mma16816(O[2*n16],   pfh[kc], vh4[0], vh4[1]);
                mma16816(O[2*n16+1], pfh[kc], vh4[2], vh4[3]);
                mma16816(O[2*n16],   pfh[kc], vl4[0], vl4[1]);
                mma16816(O[2*n16+1], pfh[kc], vl4[2], vl4[3]);
                mma16816(O[2*n16],   pfl[kc], vh4[0], vh4[1]);
                mma16816(O[2*n16+1], pfl[kc], vh4[2], vh4[3]);
            }
        }
        __syncthreads();
    }

    // ---- epilogue: write hi/lo bf16 directly (fused split for GEMM2) ----
    const float inv0 = 1.f / l0, inv1 = 1.f / l1;
    const int ec = (lane & 3) << 1;
    const size_t o0 = (size_t)(b * SEQ + row0g) * D_MODEL + h * DH;
    const size_t o1 = (size_t)(b * SEQ + row1g) * D_MODEL + h * DH;
#pragma unroll
    for (int j = 0; j < 8; j++) {
        const int cu = (j * 8 + ec) >> 1;
        float a0 = O[j][0] * inv0, a1 = O[j][1] * inv0;
        float a2 = O[j][2] * inv1, a3 = O[j][3] * inv1;
        float h0, lo0, h1, lo1;
        split1(a0, h0, lo0); split1(a1, h1, lo1);
        reinterpret_cast<uint32_t*>(outh + o0)[cu] = bf2pack(h0, h1);
        reinterpret_cast<uint32_t*>(outl + o0)[cu] = bf2pack(lo0, lo1);
        split1(a2, h0, lo0); split1(a3, h1, lo1);
        reinterpret_cast<uint32_t*>(outh + o1)[cu] = bf2pack(h0, h1);
        reinterpret_cast<uint32_t*>(outl + o1)[cu] = bf2pack(lo0, lo1);
    }
}

// ---------------------------------------------------------------------------
extern "C" void kernel_launch(void* const* d_in, const int* in_sizes, int n_in,
                              void* d_out, int out_size)
{
    const float* x     = (const float*)d_in[0];
    const float* W_in  = (const float*)d_in[1];
    const float* W_out = (const float*)d_in[2];
    float* out = (float*)d_out;

    float* qkv_buf;
    __nv_bfloat16 *ah, *al, *bh, *bl;
    cudaGetSymbolAddress((void**)&qkv_buf, g_qkv);
    cudaGetSymbolAddress((void**)&ah, g_ah);
    cudaGetSymbolAddress((void**)&al, g_al);
    cudaGetSymbolAddress((void**)&bh, g_bh);
    cudaGetSymbolAddress((void**)&bl, g_bl);

    cudaFuncSetAttribute(gemm_hmma, cudaFuncAttributeMaxDynamicSharedMemorySize, GEMM_SMEM);

    {   // split x -> bf16 hi/lo
        int n4 = MTOT * D_MODEL / 4;
        split_kernel<<<(n4 + 255) / 256, 256>>>(x, ah, al, n4);
    }
    {   // W_in -> [3072,1024] hi/lo
        dim3 grid(D3 / 32, D_MODEL / 32);
        transpose_split_kernel<<<grid, dim3(32, 8)>>>(W_in, bh, bl, D_MODEL, D3);
    }
    {   // qkv = x @ W_in  (HMMA bf16x3)
        dim3 grid(D3 / 128, MTOT / 128);
        gemm_hmma<<<grid, 256, GEMM_SMEM>>>(ah, al, bh, bl, qkv_buf, MTOT, D3, D_MODEL);
    }
    {   // causal MHA -> hi/lo bf16 (fused split)
        dim3 grid(SEQ / 128, NHEAD, BATCH);
        attn_mma_kernel<<<grid, 256>>>(qkv_buf, ah, al);
    }
    {   // W_out -> [1024,1024] hi/lo (reuses bh/bl after GEMM1 done)
        dim3 grid(D_MODEL / 32, D_MODEL / 32);
        transpose_split_kernel<<<grid, dim3(32, 8)>>>(W_out, bh, bl, D_MODEL, D_MODEL);
    }
    {   // out = attn @ W_out  (HMMA bf16x3)
        dim3 grid(D_MODEL / 128, MTOT / 128);
        gemm_hmma<<<grid, 256, GEMM_SMEM>>>(ah, al, bh, bl, out, MTOT, D_MODEL, D_MODEL);
    }
}